// round 11
// baseline (speedup 1.0000x reference)
#include <cuda_runtime.h>

#define NMAX 50000
#define EMAX 800000
#define DD 64
#define NPB 64            // dst nodes per block
#define AP 64             // sA pitch (row-major [node][k])
#define WP 68             // sW pitch (transposed [k][j])
#define SCAN_CHUNK 1024
#define MAXB ((NMAX + SCAN_CHUNK - 1) / SCAN_CHUNK)   // 49

// -------- device scratch (no allocations allowed) --------
__device__ int   g_is64;
__device__ int   g_dst[EMAX];
__device__ int   g_deg[NMAX];
__device__ int   g_rowptr[NMAX + 2];
__device__ int   g_cursor[NMAX];
__device__ int   g_col[EMAX];
__device__ int   g_bsum[MAXB + 1];
__device__ float g_h1[(size_t)NMAX * DD];

// ---- packed f32x2 helpers (sm_103a; ptxas never auto-emits FFMA2) ----
__device__ __forceinline__ unsigned long long bcast2(float a) {
    unsigned long long r;
    asm("mov.b64 %0, {%1, %1};" : "=l"(r) : "f"(a));
    return r;
}
__device__ __forceinline__ void fma2(unsigned long long& acc,
                                     unsigned long long a, unsigned long long b) {
    asm("fma.rn.f32x2 %0, %1, %2, %0;" : "+l"(acc) : "l"(a), "l"(b));
}
__device__ __forceinline__ void add2(unsigned long long& acc, unsigned long long b) {
    asm("add.rn.f32x2 %0, %0, %1;" : "+l"(acc) : "l"(b));
}
__device__ __forceinline__ void unpack2(unsigned long long p, float& lo, float& hi) {
    asm("mov.b64 {%0, %1}, %2;" : "=f"(lo), "=f"(hi) : "l"(p));
}

// ============ init deg + edge dtype detection (fused) ============
__global__ void detect_init_kernel(const void* __restrict__ edge, int n) {
    int i = blockIdx.x * blockDim.x + threadIdx.x;
    if (i < n) g_deg[i] = 0;
    if (i == 0) {
        const long long* p = (const long long*)edge;
        int ok = 1;
        for (int k = 0; k < 64; k++) {
            long long v = p[k];
            if (v < 0 || v >= n) { ok = 0; break; }
        }
        g_is64 = ok;
    }
}

// Materialize clamped int32 dst AND count degrees in one pass.
__global__ void convert_count_kernel(const void* __restrict__ edge, int e, int n) {
    int i = blockIdx.x * blockDim.x + threadIdx.x;
    if (i >= e) return;
    int d;
    if (g_is64) d = (int)((const long long*)edge)[e + i];
    else        d = ((const int*)edge)[e + i];
    d = min(max(d, 0), n - 1);
    g_dst[i] = d;
    atomicAdd(&g_deg[d], 1);
}

// ============ coalesced scan: bsum -> scan (block offsets inlined) ============
__global__ void bsum_kernel(int n) {
    __shared__ int ws[32];
    int b = blockIdx.x, t = threadIdx.x;
    int lane = t & 31, wid = t >> 5;
    int i = b * SCAN_CHUNK + t;
    int v = (i < n) ? g_deg[i] : 0;
    #pragma unroll
    for (int o = 16; o > 0; o >>= 1) v += __shfl_xor_sync(0xffffffffu, v, o);
    if (lane == 0) ws[wid] = v;
    __syncthreads();
    if (t < 32) {
        int s = ws[t];
        #pragma unroll
        for (int o = 16; o > 0; o >>= 1) s += __shfl_xor_sync(0xffffffffu, s, o);
        if (t == 0) g_bsum[b] = s;
    }
}

// per-chunk exclusive scan; block offset computed in-kernel from g_bsum
__global__ void scan_kernel(int n, int e) {
    __shared__ int ws[32];
    __shared__ int sOff;
    int b = blockIdx.x, t = threadIdx.x;
    int lane = t & 31, wid = t >> 5;

    if (wid == 0) {
        int off = 0;
        for (int j = lane; j < b; j += 32) off += g_bsum[j];
        #pragma unroll
        for (int o = 16; o > 0; o >>= 1) off += __shfl_xor_sync(0xffffffffu, off, o);
        if (lane == 0) sOff = off;
    }

    int i = b * SCAN_CHUNK + t;
    int v = (i < n) ? g_deg[i] : 0;
    int x = v;
    #pragma unroll
    for (int o = 1; o < 32; o <<= 1) {
        int y = __shfl_up_sync(0xffffffffu, x, o);
        if (lane >= o) x += y;
    }
    if (lane == 31) ws[wid] = x;
    __syncthreads();
    if (wid == 0) {
        int w = ws[lane];
        #pragma unroll
        for (int o = 1; o < 32; o <<= 1) {
            int y = __shfl_up_sync(0xffffffffu, w, o);
            if (lane >= o) w += y;
        }
        ws[lane] = w;
    }
    __syncthreads();
    int incl = x + (wid > 0 ? ws[wid - 1] : 0);
    int excl = incl - v + sOff;
    if (i < n) { g_rowptr[i] = excl; g_cursor[i] = excl; }
    if (b == 0 && t == 0) g_rowptr[n] = e;
}

// src index converted inline from the edge buffer (no g_src array)
__global__ void fill_kernel(const void* __restrict__ edge, int e, int n) {
    int i = blockIdx.x * blockDim.x + threadIdx.x;
    if (i < e) {
        int s;
        if (g_is64) s = (int)((const long long*)edge)[i];
        else        s = ((const int*)edge)[i];
        s = min(max(s, 0), n - 1);
        int p = atomicAdd(&g_cursor[g_dst[i]], 1);
        g_col[p] = s;
    }
}

// ================= fused layer =================
// mode 0: in = x param, out = g_h1, epilogue leaky_relu(0.01)
// mode 1: in = g_h1,    out = out param, epilogue row-L2-normalize
__global__ __launch_bounds__(256) void layer_kernel(
    const float* __restrict__ in_p,
    const float* __restrict__ Wl,      // [64,64] row-major
    const float* __restrict__ bias,    // [64]
    const float* __restrict__ Wr,      // [64,64] row-major
    float* __restrict__ out_p,
    int n, int mode)
{
    __shared__ float sA[NPB * AP];     // [64 nodes][64 k] row-major
    __shared__ float sW[64 * WP];      // [64 k][64 j] transposed weight
    __shared__ float sB[64];

    const float* __restrict__ in = (mode == 0) ? in_p : g_h1;
    float* __restrict__ out      = (mode == 0) ? g_h1 : out_p;

    const unsigned full = 0xffffffffu;
    int t = threadIdx.x;
    int wid = t >> 5, lane = t & 31;
    int half = lane >> 4;        // 0/1: which edge of the pair
    int c4 = (lane & 15) * 4;    // float4 column group
    int node0 = blockIdx.x * NPB;

    // load Wl^T and bias
    for (int idx = t; idx < 64 * 64; idx += 256) {
        int j = idx >> 6, k = idx & 63;
        sW[k * WP + j] = Wl[idx];
    }
    if (t < 64) sB[t] = bias[t];

    // ---- prefetch rowptr for this warp's 8 nodes (lanes 0..15) ----
    int pidx;
    if (lane < 8)       pidx = node0 + wid + lane * 8;
    else if (lane < 16) pidx = node0 + wid + (lane - 8) * 8 + 1;
    else                pidx = n;
    pidx = min(pidx, n);
    int rp = g_rowptr[pidx];

    // ---- prefetch self rows x[node] for all 8 nodes ----
    float2 xs[8];
    #pragma unroll
    for (int it = 0; it < 8; it++) {
        int node = min(node0 + wid + it * 8, n - 1);
        xs[it] = *(const float2*)&in[(size_t)node * 64 + 2 * lane];
    }

    // ---- phase 1: mean aggregation -> sA ----
    // Per <=32-edge chunk: ONE coalesced index LDG (lane i -> edge beg+i),
    // then shfl-distribute; all feature LDG.128s independent (MLP up to 16).
    #pragma unroll
    for (int it = 0; it < 8; it++) {
        int ni = wid + it * 8;
        int node = node0 + ni;
        float4 a0 = {0.f, 0.f, 0.f, 0.f};
        int beg = __shfl_sync(full, rp, it);
        int end = __shfl_sync(full, rp, it + 8);
        if (node < n) {
            for (int base = beg; base < end; base += 32) {
                int m = end - base;
                if (m > 32) m = 32;
                int gi = base + lane;
                int idx = g_col[(gi < end) ? gi : (end - 1)];
                int rounds = (m + 1) >> 1;        // uniform across warp
                #pragma unroll 4
                for (int j = 0; j < rounds; j++) {
                    int eidx = 2 * j + half;
                    int sa = __shfl_sync(full, idx, eidx);
                    float4 v = *(const float4*)&in[(size_t)sa * 64 + c4];
                    if (eidx < m) {
                        a0.x += v.x; a0.y += v.y; a0.z += v.z; a0.w += v.w;
                    }
                }
            }
            // combine the two half-warps (same columns, different edges)
            a0.x += __shfl_xor_sync(full, a0.x, 16);
            a0.y += __shfl_xor_sync(full, a0.y, 16);
            a0.z += __shfl_xor_sync(full, a0.z, 16);
            a0.w += __shfl_xor_sync(full, a0.w, 16);
            int deg = end - beg;
            float inv = 1.0f / (float)(deg > 0 ? deg : 1);
            a0.x *= inv; a0.y *= inv; a0.z *= inv; a0.w *= inv;
        }
        if (half == 0)
            *(float4*)&sA[ni * AP + c4] = a0;
    }
    __syncthreads();

    // ---- GEMM with packed f32x2 accumulators (4x4 tile) ----
    int rg = t >> 4, cg = t & 15;
    int i0 = rg * 4, j0 = cg * 4;
    unsigned long long accp[4][2] = {};

    // pass 1: acc += mean @ Wl^T
    #pragma unroll 4
    for (int k = 0; k < 64; k += 4) {
        float4 a0 = *(const float4*)&sA[(i0 + 0) * AP + k];
        float4 a1 = *(const float4*)&sA[(i0 + 1) * AP + k];
        float4 a2 = *(const float4*)&sA[(i0 + 2) * AP + k];
        float4 a3 = *(const float4*)&sA[(i0 + 3) * AP + k];
        #pragma unroll
        for (int kk = 0; kk < 4; kk++) {
            ulonglong2 wp = *(const ulonglong2*)&sW[(k + kk) * WP + j0];
            float s0 = (kk == 0) ? a0.x : (kk == 1) ? a0.y : (kk == 2) ? a0.z : a0.w;
            float s1 = (kk == 0) ? a1.x : (kk == 1) ? a1.y : (kk == 2) ? a1.z : a1.w;
            float s2 = (kk == 0) ? a2.x : (kk == 1) ? a2.y : (kk == 2) ? a2.z : a2.w;
            float s3 = (kk == 0) ? a3.x : (kk == 1) ? a3.y : (kk == 2) ? a3.z : a3.w;
            unsigned long long p;
            p = bcast2(s0); fma2(accp[0][0], p, wp.x); fma2(accp[0][1], p, wp.y);
            p = bcast2(s1); fma2(accp[1][0], p, wp.x); fma2(accp[1][1], p, wp.y);
            p = bcast2(s2); fma2(accp[2][0], p, wp.x); fma2(accp[2][1], p, wp.y);
            p = bcast2(s3); fma2(accp[3][0], p, wp.x); fma2(accp[3][1], p, wp.y);
        }
    }
    __syncthreads();

    // swap operands: sA <- x, sW <- Wr^T
    #pragma unroll
    for (int it = 0; it < 8; it++) {
        int ni = wid + it * 8;
        *(float2*)&sA[ni * AP + 2 * lane] = xs[it];
    }
    for (int idx = t; idx < 64 * 64; idx += 256) {
        int j = idx >> 6, k = idx & 63;
        sW[k * WP + j] = Wr[idx];
    }
    __syncthreads();

    // pass 2: acc += x @ Wr^T
    #pragma unroll 4
    for (int k = 0; k < 64; k += 4) {
        float4 a0 = *(const float4*)&sA[(i0 + 0) * AP + k];
        float4 a1 = *(const float4*)&sA[(i0 + 1) * AP + k];
        float4 a2 = *(const float4*)&sA[(i0 + 2) * AP + k];
        float4 a3 = *(const float4*)&sA[(i0 + 3) * AP + k];
        #pragma unroll
        for (int kk = 0; kk < 4; kk++) {
            ulonglong2 wp = *(const ulonglong2*)&sW[(k + kk) * WP + j0];
            float s0 = (kk == 0) ? a0.x : (kk == 1) ? a0.y : (kk == 2) ? a0.z : a0.w;
            float s1 = (kk == 0) ? a1.x : (kk == 1) ? a1.y : (kk == 2) ? a1.z : a1.w;
            float s2 = (kk == 0) ? a2.x : (kk == 1) ? a2.y : (kk == 2) ? a2.z : a2.w;
            float s3 = (kk == 0) ? a3.x : (kk == 1) ? a3.y : (kk == 2) ? a3.z : a3.w;
            unsigned long long p;
            p = bcast2(s0); fma2(accp[0][0], p, wp.x); fma2(accp[0][1], p, wp.y);
            p = bcast2(s1); fma2(accp[1][0], p, wp.x); fma2(accp[1][1], p, wp.y);
            p = bcast2(s2); fma2(accp[2][0], p, wp.x); fma2(accp[2][1], p, wp.y);
            p = bcast2(s3); fma2(accp[3][0], p, wp.x); fma2(accp[3][1], p, wp.y);
        }
    }

    // bias (packed) + unpack
    ulonglong2 bp = *(const ulonglong2*)&sB[j0];
    float acc[4][4];
    #pragma unroll
    for (int r = 0; r < 4; r++) {
        add2(accp[r][0], bp.x);
        add2(accp[r][1], bp.y);
        unpack2(accp[r][0], acc[r][0], acc[r][1]);
        unpack2(accp[r][1], acc[r][2], acc[r][3]);
    }

    if (mode == 0) {
        #pragma unroll
        for (int r = 0; r < 4; r++) {
            int node = node0 + i0 + r;
            if (node < n) {
                float4 st; float v;
                v = acc[r][0]; st.x = (v >= 0.f) ? v : 0.01f * v;
                v = acc[r][1]; st.y = (v >= 0.f) ? v : 0.01f * v;
                v = acc[r][2]; st.z = (v >= 0.f) ? v : 0.01f * v;
                v = acc[r][3]; st.w = (v >= 0.f) ? v : 0.01f * v;
                *(float4*)&out[(size_t)node * 64 + j0] = st;
            }
        }
    } else {
        // stage into sA, per-row L2 normalize
        __syncthreads();
        #pragma unroll
        for (int r = 0; r < 4; r++)
            *(float4*)&sA[(i0 + r) * AP + j0] =
                make_float4(acc[r][0], acc[r][1], acc[r][2], acc[r][3]);
        __syncthreads();
        #pragma unroll
        for (int it = 0; it < 8; it++) {
            int ni = wid + it * 8;
            int node = node0 + ni;
            if (node >= n) continue;
            float2 v = *(const float2*)&sA[ni * AP + 2 * lane];
            float ss = v.x * v.x + v.y * v.y;
            #pragma unroll
            for (int o = 16; o > 0; o >>= 1)
                ss += __shfl_xor_sync(full, ss, o);
            float s = 1.0f / fmaxf(sqrtf(ss), 1e-12f);
            *(float2*)&out[(size_t)node * 64 + 2 * lane] =
                make_float2(v.x * s, v.y * s);
        }
    }
}

// ================= launch (kernels ONLY — no host API calls) =================
extern "C" void kernel_launch(void* const* d_in, const int* in_sizes, int n_in,
                              void* d_out, int out_size)
{
    const float* x    = (const float*)d_in[0];
    const void*  edge = (const void*)d_in[1];
    // d_in[2] = edge_weight (ignored by SAGEConv)
    const float* W1l = (const float*)d_in[3];
    const float* b1  = (const float*)d_in[4];
    const float* W1r = (const float*)d_in[5];
    const float* W2l = (const float*)d_in[6];
    const float* b2  = (const float*)d_in[7];
    const float* W2r = (const float*)d_in[8];
    float* out = (float*)d_out;

    int n = in_sizes[0] / DD;
    int e = in_sizes[1] / 2;
    int nb = (n + SCAN_CHUNK - 1) / SCAN_CHUNK;

    detect_init_kernel<<<(n + 255) / 256, 256>>>(edge, n);
    convert_count_kernel<<<(e + 255) / 256, 256>>>(edge, e, n);
    bsum_kernel<<<nb, SCAN_CHUNK>>>(n);
    scan_kernel<<<nb, SCAN_CHUNK>>>(n, e);
    fill_kernel<<<(e + 255) / 256, 256>>>(edge, e, n);

    int nblocks = (n + NPB - 1) / NPB;
    layer_kernel<<<nblocks, 256>>>(x, W1l, b1, W1r, nullptr, n, 0); // -> g_h1
    layer_kernel<<<nblocks, 256>>>(x, W2l, b2, W2r, out,     n, 1); // g_h1 -> out
}

// round 12
// speedup vs baseline: 1.1105x; 1.1105x over previous
#include <cuda_runtime.h>

#define NMAX 50000
#define EMAX 800000
#define DD 64
#define NPB 64            // dst nodes per block
#define AP 64             // sA pitch (row-major [node][k])
#define WP 68             // sW pitch (transposed [k][j])
#define SCAN_CHUNK 1024
#define MAXB ((NMAX + SCAN_CHUNK - 1) / SCAN_CHUNK)   // 49

// -------- device scratch (no allocations allowed) --------
__device__ int   g_is64;
__device__ int   g_src[EMAX];
__device__ int   g_dst[EMAX];
__device__ int   g_deg[NMAX];
__device__ int   g_rowptr[NMAX + 2];
__device__ int   g_cursor[NMAX];
__device__ int   g_col[EMAX];
__device__ int   g_bsum[MAXB + 1];
__device__ float g_h1[(size_t)NMAX * DD];

// ---- packed f32x2 helpers (sm_103a; ptxas never auto-emits FFMA2) ----
__device__ __forceinline__ unsigned long long bcast2(float a) {
    unsigned long long r;
    asm("mov.b64 %0, {%1, %1};" : "=l"(r) : "f"(a));
    return r;
}
__device__ __forceinline__ void fma2(unsigned long long& acc,
                                     unsigned long long a, unsigned long long b) {
    asm("fma.rn.f32x2 %0, %1, %2, %0;" : "+l"(acc) : "l"(a), "l"(b));
}
__device__ __forceinline__ void add2(unsigned long long& acc, unsigned long long b) {
    asm("add.rn.f32x2 %0, %0, %1;" : "+l"(acc) : "l"(b));
}
__device__ __forceinline__ void unpack2(unsigned long long p, float& lo, float& hi) {
    asm("mov.b64 {%0, %1}, %2;" : "=f"(lo), "=f"(hi) : "l"(p));
}

// ============ init deg + edge dtype detection (fused) ============
__global__ void detect_init_kernel(const void* __restrict__ edge, int n) {
    int i = blockIdx.x * blockDim.x + threadIdx.x;
    if (i < n) g_deg[i] = 0;
    if (i == 0) {
        const long long* p = (const long long*)edge;
        int ok = 1;
        for (int k = 0; k < 64; k++) {
            long long v = p[k];
            if (v < 0 || v >= n) { ok = 0; break; }
        }
        g_is64 = ok;
    }
}

// Materialize clamped int32 src/dst AND count degrees in one pass.
__global__ void convert_count_kernel(const void* __restrict__ edge, int e, int n) {
    int i = blockIdx.x * blockDim.x + threadIdx.x;
    if (i >= e) return;
    int s, d;
    if (g_is64) {
        const long long* p = (const long long*)edge;
        s = (int)p[i];
        d = (int)p[e + i];
    } else {
        const int* p = (const int*)edge;
        s = p[i];
        d = p[e + i];
    }
    s = min(max(s, 0), n - 1);
    d = min(max(d, 0), n - 1);
    g_src[i] = s;
    g_dst[i] = d;
    atomicAdd(&g_deg[d], 1);
}

// ============ coalesced scan: bsum -> scan (block offsets inlined) ============
__global__ void bsum_kernel(int n) {
    __shared__ int ws[32];
    int b = blockIdx.x, t = threadIdx.x;
    int lane = t & 31, wid = t >> 5;
    int i = b * SCAN_CHUNK + t;
    int v = (i < n) ? g_deg[i] : 0;
    #pragma unroll
    for (int o = 16; o > 0; o >>= 1) v += __shfl_xor_sync(0xffffffffu, v, o);
    if (lane == 0) ws[wid] = v;
    __syncthreads();
    if (t < 32) {
        int s = ws[t];
        #pragma unroll
        for (int o = 16; o > 0; o >>= 1) s += __shfl_xor_sync(0xffffffffu, s, o);
        if (t == 0) g_bsum[b] = s;
    }
}

// per-chunk exclusive scan; block offset computed in-kernel from g_bsum
__global__ void scan_kernel(int n, int e) {
    __shared__ int ws[32];
    __shared__ int sOff;
    int b = blockIdx.x, t = threadIdx.x;
    int lane = t & 31, wid = t >> 5;

    if (wid == 0) {
        int off = 0;
        for (int j = lane; j < b; j += 32) off += g_bsum[j];
        #pragma unroll
        for (int o = 16; o > 0; o >>= 1) off += __shfl_xor_sync(0xffffffffu, off, o);
        if (lane == 0) sOff = off;
    }

    int i = b * SCAN_CHUNK + t;
    int v = (i < n) ? g_deg[i] : 0;
    int x = v;
    #pragma unroll
    for (int o = 1; o < 32; o <<= 1) {
        int y = __shfl_up_sync(0xffffffffu, x, o);
        if (lane >= o) x += y;
    }
    if (lane == 31) ws[wid] = x;
    __syncthreads();
    if (wid == 0) {
        int w = ws[lane];
        #pragma unroll
        for (int o = 1; o < 32; o <<= 1) {
            int y = __shfl_up_sync(0xffffffffu, w, o);
            if (lane >= o) w += y;
        }
        ws[lane] = w;
    }
    __syncthreads();
    int incl = x + (wid > 0 ? ws[wid - 1] : 0);
    int excl = incl - v + sOff;
    if (i < n) { g_rowptr[i] = excl; g_cursor[i] = excl; }
    if (b == 0 && t == 0) g_rowptr[n] = e;
}

__global__ void fill_kernel(int e) {
    int i = blockIdx.x * blockDim.x + threadIdx.x;
    if (i < e) {
        int p = atomicAdd(&g_cursor[g_dst[i]], 1);
        g_col[p] = g_src[i];
    }
}

// ================= fused layer =================
// mode 0: in = x param, out = g_h1, epilogue leaky_relu(0.01)
// mode 1: in = g_h1,    out = out param, epilogue row-L2-normalize
__global__ __launch_bounds__(256) void layer_kernel(
    const float* __restrict__ in_p,
    const float* __restrict__ Wl,      // [64,64] row-major
    const float* __restrict__ bias,    // [64]
    const float* __restrict__ Wr,      // [64,64] row-major
    float* __restrict__ out_p,
    int n, int mode)
{
    __shared__ float sA[NPB * AP];     // [64 nodes][64 k] row-major
    __shared__ float sW[64 * WP];      // [64 k][64 j] transposed weight
    __shared__ float sB[64];

    const float* __restrict__ in = (mode == 0) ? in_p : g_h1;
    float* __restrict__ out      = (mode == 0) ? g_h1 : out_p;

    const unsigned full = 0xffffffffu;
    int t = threadIdx.x;
    int wid = t >> 5, lane = t & 31;
    int half = lane >> 4;        // 0/1: which edge of the pair
    int c4 = (lane & 15) * 4;    // float4 column group
    int node0 = blockIdx.x * NPB;

    // load Wl^T and bias
    for (int idx = t; idx < 64 * 64; idx += 256) {
        int j = idx >> 6, k = idx & 63;
        sW[k * WP + j] = Wl[idx];
    }
    if (t < 64) sB[t] = bias[t];

    // ---- prefetch rowptr for this warp's 8 nodes (lanes 0..15) ----
    // Out-of-range nodes clamp to rowptr[n] for BOTH beg and end -> deg 0.
    int pidx;
    if (lane < 8)       pidx = node0 + wid + lane * 8;
    else if (lane < 16) pidx = node0 + wid + (lane - 8) * 8 + 1;
    else                pidx = n;
    pidx = min(pidx, n);
    int rp = g_rowptr[pidx];

    // ---- prefetch self rows x[node] for all 8 nodes ----
    float2 xs[8];
    #pragma unroll
    for (int it = 0; it < 8; it++) {
        int node = min(node0 + wid + it * 8, n - 1);
        xs[it] = *(const float2*)&in[(size_t)node * 64 + 2 * lane];
    }

    // ---- phase 1: mean aggregation, TWO nodes interleaved per warp ----
    // Pairs (it, it+4): joint loop keeps 4 index + 4 feature LDGs in flight.
    #pragma unroll
    for (int it = 0; it < 4; it++) {
        int itb = it + 4;
        int nia = wid + it * 8;
        int nib = wid + itb * 8;
        int begA = __shfl_sync(full, rp, it),  endA = __shfl_sync(full, rp, it + 8);
        int begB = __shfl_sync(full, rp, itb), endB = __shfl_sync(full, rp, itb + 8);

        float4 A0 = {0.f,0.f,0.f,0.f}, A1 = {0.f,0.f,0.f,0.f};
        float4 B0 = {0.f,0.f,0.f,0.f}, B1 = {0.f,0.f,0.f,0.f};
        int ea = begA, eb = begB;

        // joint main loop: 4 edges per node per iteration (uniform across warp)
        while (ea + 4 <= endA && eb + 4 <= endB) {
            int sa0 = g_col[ea + half];
            int sa1 = g_col[ea + 2 + half];
            int sb0 = g_col[eb + half];
            int sb1 = g_col[eb + 2 + half];
            float4 va0 = *(const float4*)&in[(size_t)sa0 * 64 + c4];
            float4 va1 = *(const float4*)&in[(size_t)sa1 * 64 + c4];
            float4 vb0 = *(const float4*)&in[(size_t)sb0 * 64 + c4];
            float4 vb1 = *(const float4*)&in[(size_t)sb1 * 64 + c4];
            A0.x += va0.x; A0.y += va0.y; A0.z += va0.z; A0.w += va0.w;
            A1.x += va1.x; A1.y += va1.y; A1.z += va1.z; A1.w += va1.w;
            B0.x += vb0.x; B0.y += vb0.y; B0.z += vb0.z; B0.w += vb0.w;
            B1.x += vb1.x; B1.y += vb1.y; B1.z += vb1.z; B1.w += vb1.w;
            ea += 4; eb += 4;
        }
        // drain node A
        for (; ea + 4 <= endA; ea += 4) {
            int sa0 = g_col[ea + half];
            int sa1 = g_col[ea + 2 + half];
            float4 v0 = *(const float4*)&in[(size_t)sa0 * 64 + c4];
            float4 v1 = *(const float4*)&in[(size_t)sa1 * 64 + c4];
            A0.x += v0.x; A0.y += v0.y; A0.z += v0.z; A0.w += v0.w;
            A1.x += v1.x; A1.y += v1.y; A1.z += v1.z; A1.w += v1.w;
        }
        if (ea + 2 <= endA) {
            int sa = g_col[ea + half];
            float4 v = *(const float4*)&in[(size_t)sa * 64 + c4];
            A0.x += v.x; A0.y += v.y; A0.z += v.z; A0.w += v.w;
            ea += 2;
        }
        if (ea < endA && half == 0) {
            int sa = g_col[ea];
            float4 v = *(const float4*)&in[(size_t)sa * 64 + c4];
            A1.x += v.x; A1.y += v.y; A1.z += v.z; A1.w += v.w;
        }
        // drain node B
        for (; eb + 4 <= endB; eb += 4) {
            int sb0 = g_col[eb + half];
            int sb1 = g_col[eb + 2 + half];
            float4 v0 = *(const float4*)&in[(size_t)sb0 * 64 + c4];
            float4 v1 = *(const float4*)&in[(size_t)sb1 * 64 + c4];
            B0.x += v0.x; B0.y += v0.y; B0.z += v0.z; B0.w += v0.w;
            B1.x += v1.x; B1.y += v1.y; B1.z += v1.z; B1.w += v1.w;
        }
        if (eb + 2 <= endB) {
            int sb = g_col[eb + half];
            float4 v = *(const float4*)&in[(size_t)sb * 64 + c4];
            B0.x += v.x; B0.y += v.y; B0.z += v.z; B0.w += v.w;
            eb += 2;
        }
        if (eb < endB && half == 0) {
            int sb = g_col[eb];
            float4 v = *(const float4*)&in[(size_t)sb * 64 + c4];
            B1.x += v.x; B1.y += v.y; B1.z += v.z; B1.w += v.w;
        }

        // reduce + normalize node A
        A0.x += A1.x; A0.y += A1.y; A0.z += A1.z; A0.w += A1.w;
        A0.x += __shfl_xor_sync(full, A0.x, 16);
        A0.y += __shfl_xor_sync(full, A0.y, 16);
        A0.z += __shfl_xor_sync(full, A0.z, 16);
        A0.w += __shfl_xor_sync(full, A0.w, 16);
        int degA = endA - begA;
        float invA = 1.0f / (float)(degA > 0 ? degA : 1);
        A0.x *= invA; A0.y *= invA; A0.z *= invA; A0.w *= invA;
        // reduce + normalize node B
        B0.x += B1.x; B0.y += B1.y; B0.z += B1.z; B0.w += B1.w;
        B0.x += __shfl_xor_sync(full, B0.x, 16);
        B0.y += __shfl_xor_sync(full, B0.y, 16);
        B0.z += __shfl_xor_sync(full, B0.z, 16);
        B0.w += __shfl_xor_sync(full, B0.w, 16);
        int degB = endB - begB;
        float invB = 1.0f / (float)(degB > 0 ? degB : 1);
        B0.x *= invB; B0.y *= invB; B0.z *= invB; B0.w *= invB;

        if (half == 0) {
            *(float4*)&sA[nia * AP + c4] = A0;
            *(float4*)&sA[nib * AP + c4] = B0;
        }
    }
    __syncthreads();

    // ---- GEMM with packed f32x2 accumulators (4x4 tile) ----
    int rg = t >> 4, cg = t & 15;
    int i0 = rg * 4, j0 = cg * 4;
    unsigned long long accp[4][2] = {};

    // pass 1: acc += mean @ Wl^T
    #pragma unroll 4
    for (int k = 0; k < 64; k += 4) {
        float4 a0 = *(const float4*)&sA[(i0 + 0) * AP + k];
        float4 a1 = *(const float4*)&sA[(i0 + 1) * AP + k];
        float4 a2 = *(const float4*)&sA[(i0 + 2) * AP + k];
        float4 a3 = *(const float4*)&sA[(i0 + 3) * AP + k];
        #pragma unroll
        for (int kk = 0; kk < 4; kk++) {
            ulonglong2 wp = *(const ulonglong2*)&sW[(k + kk) * WP + j0];
            float s0 = (kk == 0) ? a0.x : (kk == 1) ? a0.y : (kk == 2) ? a0.z : a0.w;
            float s1 = (kk == 0) ? a1.x : (kk == 1) ? a1.y : (kk == 2) ? a1.z : a1.w;
            float s2 = (kk == 0) ? a2.x : (kk == 1) ? a2.y : (kk == 2) ? a2.z : a2.w;
            float s3 = (kk == 0) ? a3.x : (kk == 1) ? a3.y : (kk == 2) ? a3.z : a3.w;
            unsigned long long p;
            p = bcast2(s0); fma2(accp[0][0], p, wp.x); fma2(accp[0][1], p, wp.y);
            p = bcast2(s1); fma2(accp[1][0], p, wp.x); fma2(accp[1][1], p, wp.y);
            p = bcast2(s2); fma2(accp[2][0], p, wp.x); fma2(accp[2][1], p, wp.y);
            p = bcast2(s3); fma2(accp[3][0], p, wp.x); fma2(accp[3][1], p, wp.y);
        }
    }
    __syncthreads();

    // swap operands: sA <- x, sW <- Wr^T
    #pragma unroll
    for (int it = 0; it < 8; it++) {
        int ni = wid + it * 8;
        *(float2*)&sA[ni * AP + 2 * lane] = xs[it];
    }
    for (int idx = t; idx < 64 * 64; idx += 256) {
        int j = idx >> 6, k = idx & 63;
        sW[k * WP + j] = Wr[idx];
    }
    __syncthreads();

    // pass 2: acc += x @ Wr^T
    #pragma unroll 4
    for (int k = 0; k < 64; k += 4) {
        float4 a0 = *(const float4*)&sA[(i0 + 0) * AP + k];
        float4 a1 = *(const float4*)&sA[(i0 + 1) * AP + k];
        float4 a2 = *(const float4*)&sA[(i0 + 2) * AP + k];
        float4 a3 = *(const float4*)&sA[(i0 + 3) * AP + k];
        #pragma unroll
        for (int kk = 0; kk < 4; kk++) {
            ulonglong2 wp = *(const ulonglong2*)&sW[(k + kk) * WP + j0];
            float s0 = (kk == 0) ? a0.x : (kk == 1) ? a0.y : (kk == 2) ? a0.z : a0.w;
            float s1 = (kk == 0) ? a1.x : (kk == 1) ? a1.y : (kk == 2) ? a1.z : a1.w;
            float s2 = (kk == 0) ? a2.x : (kk == 1) ? a2.y : (kk == 2) ? a2.z : a2.w;
            float s3 = (kk == 0) ? a3.x : (kk == 1) ? a3.y : (kk == 2) ? a3.z : a3.w;
            unsigned long long p;
            p = bcast2(s0); fma2(accp[0][0], p, wp.x); fma2(accp[0][1], p, wp.y);
            p = bcast2(s1); fma2(accp[1][0], p, wp.x); fma2(accp[1][1], p, wp.y);
            p = bcast2(s2); fma2(accp[2][0], p, wp.x); fma2(accp[2][1], p, wp.y);
            p = bcast2(s3); fma2(accp[3][0], p, wp.x); fma2(accp[3][1], p, wp.y);
        }
    }

    // bias (packed) + unpack
    ulonglong2 bp = *(const ulonglong2*)&sB[j0];
    float acc[4][4];
    #pragma unroll
    for (int r = 0; r < 4; r++) {
        add2(accp[r][0], bp.x);
        add2(accp[r][1], bp.y);
        unpack2(accp[r][0], acc[r][0], acc[r][1]);
        unpack2(accp[r][1], acc[r][2], acc[r][3]);
    }

    if (mode == 0) {
        #pragma unroll
        for (int r = 0; r < 4; r++) {
            int node = node0 + i0 + r;
            if (node < n) {
                float4 st; float v;
                v = acc[r][0]; st.x = (v >= 0.f) ? v : 0.01f * v;
                v = acc[r][1]; st.y = (v >= 0.f) ? v : 0.01f * v;
                v = acc[r][2]; st.z = (v >= 0.f) ? v : 0.01f * v;
                v = acc[r][3]; st.w = (v >= 0.f) ? v : 0.01f * v;
                *(float4*)&out[(size_t)node * 64 + j0] = st;
            }
        }
    } else {
        // stage into sA, per-row L2 normalize
        __syncthreads();
        #pragma unroll
        for (int r = 0; r < 4; r++)
            *(float4*)&sA[(i0 + r) * AP + j0] =
                make_float4(acc[r][0], acc[r][1], acc[r][2], acc[r][3]);
        __syncthreads();
        #pragma unroll
        for (int it = 0; it < 8; it++) {
            int ni = wid + it * 8;
            int node = node0 + ni;
            if (node >= n) continue;
            float2 v = *(const float2*)&sA[ni * AP + 2 * lane];
            float ss = v.x * v.x + v.y * v.y;
            #pragma unroll
            for (int o = 16; o > 0; o >>= 1)
                ss += __shfl_xor_sync(full, ss, o);
            float s = 1.0f / fmaxf(sqrtf(ss), 1e-12f);
            *(float2*)&out[(size_t)node * 64 + 2 * lane] =
                make_float2(v.x * s, v.y * s);
        }
    }
}

// ================= launch (kernels ONLY — no host API calls) =================
extern "C" void kernel_launch(void* const* d_in, const int* in_sizes, int n_in,
                              void* d_out, int out_size)
{
    const float* x    = (const float*)d_in[0];
    const void*  edge = (const void*)d_in[1];
    // d_in[2] = edge_weight (ignored by SAGEConv)
    const float* W1l = (const float*)d_in[3];
    const float* b1  = (const float*)d_in[4];
    const float* W1r = (const float*)d_in[5];
    const float* W2l = (const float*)d_in[6];
    const float* b2  = (const float*)d_in[7];
    const float* W2r = (const float*)d_in[8];
    float* out = (float*)d_out;

    int n = in_sizes[0] / DD;
    int e = in_sizes[1] / 2;
    int nb = (n + SCAN_CHUNK - 1) / SCAN_CHUNK;

    detect_init_kernel<<<(n + 255) / 256, 256>>>(edge, n);
    convert_count_kernel<<<(e + 255) / 256, 256>>>(edge, e, n);
    bsum_kernel<<<nb, SCAN_CHUNK>>>(n);
    scan_kernel<<<nb, SCAN_CHUNK>>>(n, e);
    fill_kernel<<<(e + 255) / 256, 256>>>(e);

    int nblocks = (n + NPB - 1) / NPB;
    layer_kernel<<<nblocks, 256>>>(x, W1l, b1, W1r, nullptr, n, 0); // -> g_h1
    layer_kernel<<<nblocks, 256>>>(x, W2l, b2, W2r, out,     n, 1); // g_h1 -> out
}

// round 13
// speedup vs baseline: 1.1426x; 1.0289x over previous
#include <cuda_runtime.h>

#define NMAX 50000
#define EMAX 800000
#define DD 64
#define NPB 64            // dst nodes per block
#define AP 64             // sA pitch (row-major [node][k])
#define WP 68             // sW pitch (transposed [k][j])
#define SCAN_CHUNK 1024
#define MAXB ((NMAX + SCAN_CHUNK - 1) / SCAN_CHUNK)   // 49
#define DSTMASK 0x1FFFF   // low 17 bits = dst id (n < 131072)

// -------- device scratch (no allocations allowed) --------
__device__ int   g_is64;
__device__ int   g_src[EMAX];
__device__ int   g_dst[EMAX];      // packed: (rank << 17) | dst
__device__ int   g_deg[NMAX];
__device__ int   g_rowptr[NMAX + 2];
__device__ int   g_col[EMAX];
__device__ int   g_bsum[MAXB + 1];
__device__ float g_h1[(size_t)NMAX * DD];

// ---- packed f32x2 helpers (sm_103a; ptxas never auto-emits FFMA2) ----
__device__ __forceinline__ unsigned long long bcast2(float a) {
    unsigned long long r;
    asm("mov.b64 %0, {%1, %1};" : "=l"(r) : "f"(a));
    return r;
}
__device__ __forceinline__ void fma2(unsigned long long& acc,
                                     unsigned long long a, unsigned long long b) {
    asm("fma.rn.f32x2 %0, %1, %2, %0;" : "+l"(acc) : "l"(a), "l"(b));
}
__device__ __forceinline__ void add2(unsigned long long& acc, unsigned long long b) {
    asm("add.rn.f32x2 %0, %0, %1;" : "+l"(acc) : "l"(b));
}
__device__ __forceinline__ void unpack2(unsigned long long p, float& lo, float& hi) {
    asm("mov.b64 {%0, %1}, %2;" : "=f"(lo), "=f"(hi) : "l"(p));
}

// ============ init deg + edge dtype detection (fused) ============
__global__ void detect_init_kernel(const void* __restrict__ edge, int n) {
    int i = blockIdx.x * blockDim.x + threadIdx.x;
    if (i < n) g_deg[i] = 0;
    if (i == 0) {
        const long long* p = (const long long*)edge;
        int ok = 1;
        for (int k = 0; k < 64; k++) {
            long long v = p[k];
            if (v < 0 || v >= n) { ok = 0; break; }
        }
        g_is64 = ok;
    }
}

// Materialize clamped int32 src + (rank-packed) dst AND count degrees.
// The degree-count atomicAdd's return value IS the edge's within-node rank.
__global__ void convert_count_kernel(const void* __restrict__ edge, int e, int n) {
    int i = blockIdx.x * blockDim.x + threadIdx.x;
    if (i >= e) return;
    int s, d;
    if (g_is64) {
        const long long* p = (const long long*)edge;
        s = (int)p[i];
        d = (int)p[e + i];
    } else {
        const int* p = (const int*)edge;
        s = p[i];
        d = p[e + i];
    }
    s = min(max(s, 0), n - 1);
    d = min(max(d, 0), n - 1);
    g_src[i] = s;
    int r = atomicAdd(&g_deg[d], 1);
    g_dst[i] = d | (r << 17);
}

// ============ coalesced scan: bsum -> scan (block offsets inlined) ============
__global__ void bsum_kernel(int n) {
    __shared__ int ws[32];
    int b = blockIdx.x, t = threadIdx.x;
    int lane = t & 31, wid = t >> 5;
    int i = b * SCAN_CHUNK + t;
    int v = (i < n) ? g_deg[i] : 0;
    #pragma unroll
    for (int o = 16; o > 0; o >>= 1) v += __shfl_xor_sync(0xffffffffu, v, o);
    if (lane == 0) ws[wid] = v;
    __syncthreads();
    if (t < 32) {
        int s = ws[t];
        #pragma unroll
        for (int o = 16; o > 0; o >>= 1) s += __shfl_xor_sync(0xffffffffu, s, o);
        if (t == 0) g_bsum[b] = s;
    }
}

// per-chunk exclusive scan; block offset computed in-kernel from g_bsum
__global__ void scan_kernel(int n, int e) {
    __shared__ int ws[32];
    __shared__ int sOff;
    int b = blockIdx.x, t = threadIdx.x;
    int lane = t & 31, wid = t >> 5;

    if (wid == 0) {
        int off = 0;
        for (int j = lane; j < b; j += 32) off += g_bsum[j];
        #pragma unroll
        for (int o = 16; o > 0; o >>= 1) off += __shfl_xor_sync(0xffffffffu, off, o);
        if (lane == 0) sOff = off;
    }

    int i = b * SCAN_CHUNK + t;
    int v = (i < n) ? g_deg[i] : 0;
    int x = v;
    #pragma unroll
    for (int o = 1; o < 32; o <<= 1) {
        int y = __shfl_up_sync(0xffffffffu, x, o);
        if (lane >= o) x += y;
    }
    if (lane == 31) ws[wid] = x;
    __syncthreads();
    if (wid == 0) {
        int w = ws[lane];
        #pragma unroll
        for (int o = 1; o < 32; o <<= 1) {
            int y = __shfl_up_sync(0xffffffffu, w, o);
            if (lane >= o) w += y;
        }
        ws[lane] = w;
    }
    __syncthreads();
    int incl = x + (wid > 0 ? ws[wid - 1] : 0);
    int excl = incl - v + sOff;
    if (i < n) g_rowptr[i] = excl;
    if (b == 0 && t == 0) g_rowptr[n] = e;
}

// atomic-free fill: slot = rowptr[dst] + rank (rank packed in g_dst)
__global__ void fill_kernel(int e) {
    int i = blockIdx.x * blockDim.x + threadIdx.x;
    if (i < e) {
        int v = g_dst[i];
        int d = v & DSTMASK;
        int r = v >> 17;
        g_col[g_rowptr[d] + r] = g_src[i];
    }
}

// ================= fused layer (round-10 winner, unchanged) =================
// mode 0: in = x param, out = g_h1, epilogue leaky_relu(0.01)
// mode 1: in = g_h1,    out = out param, epilogue row-L2-normalize
__global__ __launch_bounds__(256) void layer_kernel(
    const float* __restrict__ in_p,
    const float* __restrict__ Wl,      // [64,64] row-major
    const float* __restrict__ bias,    // [64]
    const float* __restrict__ Wr,      // [64,64] row-major
    float* __restrict__ out_p,
    int n, int mode)
{
    __shared__ float sA[NPB * AP];     // [64 nodes][64 k] row-major
    __shared__ float sW[64 * WP];      // [64 k][64 j] transposed weight
    __shared__ float sB[64];

    const float* __restrict__ in = (mode == 0) ? in_p : g_h1;
    float* __restrict__ out      = (mode == 0) ? g_h1 : out_p;

    const unsigned full = 0xffffffffu;
    int t = threadIdx.x;
    int wid = t >> 5, lane = t & 31;
    int half = lane >> 4;        // 0/1: which edge of the pair
    int c4 = (lane & 15) * 4;    // float4 column group
    int node0 = blockIdx.x * NPB;

    // load Wl^T and bias
    for (int idx = t; idx < 64 * 64; idx += 256) {
        int j = idx >> 6, k = idx & 63;
        sW[k * WP + j] = Wl[idx];
    }
    if (t < 64) sB[t] = bias[t];

    // ---- prefetch rowptr for this warp's 8 nodes (lanes 0..15) ----
    int pidx;
    if (lane < 8)       pidx = node0 + wid + lane * 8;
    else if (lane < 16) pidx = node0 + wid + (lane - 8) * 8 + 1;
    else                pidx = n;
    pidx = min(pidx, n);
    int rp = g_rowptr[pidx];

    // ---- prefetch self rows x[node] for all 8 nodes ----
    float2 xs[8];
    #pragma unroll
    for (int it = 0; it < 8; it++) {
        int node = min(node0 + wid + it * 8, n - 1);
        xs[it] = *(const float2*)&in[(size_t)node * 64 + 2 * lane];
    }

    // ---- phase 1: mean aggregation -> sA ----
    #pragma unroll
    for (int it = 0; it < 8; it++) {
        int ni = wid + it * 8;
        int node = node0 + ni;
        float4 a0 = {0.f, 0.f, 0.f, 0.f}, a1 = {0.f, 0.f, 0.f, 0.f};
        int beg = __shfl_sync(full, rp, it);
        int end = __shfl_sync(full, rp, it + 8);
        if (node < n) {
            int e0 = beg;
            for (; e0 + 4 <= end; e0 += 4) {
                int sa = g_col[e0 + half];
                int sb = g_col[e0 + 2 + half];
                float4 v0 = *(const float4*)&in[(size_t)sa * 64 + c4];
                float4 v1 = *(const float4*)&in[(size_t)sb * 64 + c4];
                a0.x += v0.x; a0.y += v0.y; a0.z += v0.z; a0.w += v0.w;
                a1.x += v1.x; a1.y += v1.y; a1.z += v1.z; a1.w += v1.w;
            }
            if (e0 + 2 <= end) {
                int sa = g_col[e0 + half];
                float4 v0 = *(const float4*)&in[(size_t)sa * 64 + c4];
                a0.x += v0.x; a0.y += v0.y; a0.z += v0.z; a0.w += v0.w;
                e0 += 2;
            }
            if (e0 < end && half == 0) {
                int sa = g_col[e0];
                float4 v0 = *(const float4*)&in[(size_t)sa * 64 + c4];
                a1.x += v0.x; a1.y += v0.y; a1.z += v0.z; a1.w += v0.w;
            }
            a0.x += a1.x; a0.y += a1.y; a0.z += a1.z; a0.w += a1.w;
            a0.x += __shfl_xor_sync(full, a0.x, 16);
            a0.y += __shfl_xor_sync(full, a0.y, 16);
            a0.z += __shfl_xor_sync(full, a0.z, 16);
            a0.w += __shfl_xor_sync(full, a0.w, 16);
            int deg = end - beg;
            float inv = 1.0f / (float)(deg > 0 ? deg : 1);
            a0.x *= inv; a0.y *= inv; a0.z *= inv; a0.w *= inv;
        }
        if (half == 0)
            *(float4*)&sA[ni * AP + c4] = a0;
    }
    __syncthreads();

    // ---- GEMM with packed f32x2 accumulators (4x4 tile) ----
    int rg = t >> 4, cg = t & 15;
    int i0 = rg * 4, j0 = cg * 4;
    unsigned long long accp[4][2] = {};

    // pass 1: acc += mean @ Wl^T
    #pragma unroll 4
    for (int k = 0; k < 64; k += 4) {
        float4 a0 = *(const float4*)&sA[(i0 + 0) * AP + k];
        float4 a1 = *(const float4*)&sA[(i0 + 1) * AP + k];
        float4 a2 = *(const float4*)&sA[(i0 + 2) * AP + k];
        float4 a3 = *(const float4*)&sA[(i0 + 3) * AP + k];
        #pragma unroll
        for (int kk = 0; kk < 4; kk++) {
            ulonglong2 wp = *(const ulonglong2*)&sW[(k + kk) * WP + j0];
            float s0 = (kk == 0) ? a0.x : (kk == 1) ? a0.y : (kk == 2) ? a0.z : a0.w;
            float s1 = (kk == 0) ? a1.x : (kk == 1) ? a1.y : (kk == 2) ? a1.z : a1.w;
            float s2 = (kk == 0) ? a2.x : (kk == 1) ? a2.y : (kk == 2) ? a2.z : a2.w;
            float s3 = (kk == 0) ? a3.x : (kk == 1) ? a3.y : (kk == 2) ? a3.z : a3.w;
            unsigned long long p;
            p = bcast2(s0); fma2(accp[0][0], p, wp.x); fma2(accp[0][1], p, wp.y);
            p = bcast2(s1); fma2(accp[1][0], p, wp.x); fma2(accp[1][1], p, wp.y);
            p = bcast2(s2); fma2(accp[2][0], p, wp.x); fma2(accp[2][1], p, wp.y);
            p = bcast2(s3); fma2(accp[3][0], p, wp.x); fma2(accp[3][1], p, wp.y);
        }
    }
    __syncthreads();

    // swap operands: sA <- x, sW <- Wr^T
    #pragma unroll
    for (int it = 0; it < 8; it++) {
        int ni = wid + it * 8;
        *(float2*)&sA[ni * AP + 2 * lane] = xs[it];
    }
    for (int idx = t; idx < 64 * 64; idx += 256) {
        int j = idx >> 6, k = idx & 63;
        sW[k * WP + j] = Wr[idx];
    }
    __syncthreads();

    // pass 2: acc += x @ Wr^T
    #pragma unroll 4
    for (int k = 0; k < 64; k += 4) {
        float4 a0 = *(const float4*)&sA[(i0 + 0) * AP + k];
        float4 a1 = *(const float4*)&sA[(i0 + 1) * AP + k];
        float4 a2 = *(const float4*)&sA[(i0 + 2) * AP + k];
        float4 a3 = *(const float4*)&sA[(i0 + 3) * AP + k];
        #pragma unroll
        for (int kk = 0; kk < 4; kk++) {
            ulonglong2 wp = *(const ulonglong2*)&sW[(k + kk) * WP + j0];
            float s0 = (kk == 0) ? a0.x : (kk == 1) ? a0.y : (kk == 2) ? a0.z : a0.w;
            float s1 = (kk == 0) ? a1.x : (kk == 1) ? a1.y : (kk == 2) ? a1.z : a1.w;
            float s2 = (kk == 0) ? a2.x : (kk == 1) ? a2.y : (kk == 2) ? a2.z : a2.w;
            float s3 = (kk == 0) ? a3.x : (kk == 1) ? a3.y : (kk == 2) ? a3.z : a3.w;
            unsigned long long p;
            p = bcast2(s0); fma2(accp[0][0], p, wp.x); fma2(accp[0][1], p, wp.y);
            p = bcast2(s1); fma2(accp[1][0], p, wp.x); fma2(accp[1][1], p, wp.y);
            p = bcast2(s2); fma2(accp[2][0], p, wp.x); fma2(accp[2][1], p, wp.y);
            p = bcast2(s3); fma2(accp[3][0], p, wp.x); fma2(accp[3][1], p, wp.y);
        }
    }

    // bias (packed) + unpack
    ulonglong2 bp = *(const ulonglong2*)&sB[j0];
    float acc[4][4];
    #pragma unroll
    for (int r = 0; r < 4; r++) {
        add2(accp[r][0], bp.x);
        add2(accp[r][1], bp.y);
        unpack2(accp[r][0], acc[r][0], acc[r][1]);
        unpack2(accp[r][1], acc[r][2], acc[r][3]);
    }

    if (mode == 0) {
        #pragma unroll
        for (int r = 0; r < 4; r++) {
            int node = node0 + i0 + r;
            if (node < n) {
                float4 st; float v;
                v = acc[r][0]; st.x = (v >= 0.f) ? v : 0.01f * v;
                v = acc[r][1]; st.y = (v >= 0.f) ? v : 0.01f * v;
                v = acc[r][2]; st.z = (v >= 0.f) ? v : 0.01f * v;
                v = acc[r][3]; st.w = (v >= 0.f) ? v : 0.01f * v;
                *(float4*)&out[(size_t)node * 64 + j0] = st;
            }
        }
    } else {
        // stage into sA, per-row L2 normalize
        __syncthreads();
        #pragma unroll
        for (int r = 0; r < 4; r++)
            *(float4*)&sA[(i0 + r) * AP + j0] =
                make_float4(acc[r][0], acc[r][1], acc[r][2], acc[r][3]);
        __syncthreads();
        #pragma unroll
        for (int it = 0; it < 8; it++) {
            int ni = wid + it * 8;
            int node = node0 + ni;
            if (node >= n) continue;
            float2 v = *(const float2*)&sA[ni * AP + 2 * lane];
            float ss = v.x * v.x + v.y * v.y;
            #pragma unroll
            for (int o = 16; o > 0; o >>= 1)
                ss += __shfl_xor_sync(full, ss, o);
            float s = 1.0f / fmaxf(sqrtf(ss), 1e-12f);
            *(float2*)&out[(size_t)node * 64 + 2 * lane] =
                make_float2(v.x * s, v.y * s);
        }
    }
}

// ================= launch (kernels ONLY — no host API calls) =================
extern "C" void kernel_launch(void* const* d_in, const int* in_sizes, int n_in,
                              void* d_out, int out_size)
{
    const float* x    = (const float*)d_in[0];
    const void*  edge = (const void*)d_in[1];
    // d_in[2] = edge_weight (ignored by SAGEConv)
    const float* W1l = (const float*)d_in[3];
    const float* b1  = (const float*)d_in[4];
    const float* W1r = (const float*)d_in[5];
    const float* W2l = (const float*)d_in[6];
    const float* b2  = (const float*)d_in[7];
    const float* W2r = (const float*)d_in[8];
    float* out = (float*)d_out;

    int n = in_sizes[0] / DD;
    int e = in_sizes[1] / 2;
    int nb = (n + SCAN_CHUNK - 1) / SCAN_CHUNK;

    detect_init_kernel<<<(n + 255) / 256, 256>>>(edge, n);
    convert_count_kernel<<<(e + 255) / 256, 256>>>(edge, e, n);
    bsum_kernel<<<nb, SCAN_CHUNK>>>(n);
    scan_kernel<<<nb, SCAN_CHUNK>>>(n, e);
    fill_kernel<<<(e + 255) / 256, 256>>>(e);

    int nblocks = (n + NPB - 1) / NPB;
    layer_kernel<<<nblocks, 256>>>(x, W1l, b1, W1r, nullptr, n, 0); // -> g_h1
    layer_kernel<<<nblocks, 256>>>(x, W2l, b2, W2r, out,     n, 1); // g_h1 -> out
}

// round 14
// speedup vs baseline: 1.1607x; 1.0158x over previous
#include <cuda_runtime.h>

#define NMAX 50000
#define EMAX 800000
#define DD 64
#define NPB 64            // dst nodes per block
#define AP 64             // sA pitch (row-major [node][k])
#define WP 68             // sW pitch (transposed [k][j])
#define SCAN_CHUNK 1024
#define MAXB ((NMAX + SCAN_CHUNK - 1) / SCAN_CHUNK)   // 49
#define DSTMASK 0x1FFFF   // low 17 bits = dst id (n < 131072)

// -------- device scratch (no allocations allowed) --------
// g_deg is zero at module load and restored to zero by scan_kernel every
// invocation -> self-restoring invariant, no init kernel needed.
__device__ int   g_src[EMAX];
__device__ int   g_dst[EMAX];      // packed: (rank << 17) | dst
__device__ int   g_deg[NMAX];
__device__ int   g_rowptr[NMAX + 2];
__device__ int   g_col[EMAX];
__device__ int   g_bsum[MAXB + 1];
__device__ float g_h1[(size_t)NMAX * DD];

// ---- packed f32x2 helpers (sm_103a; ptxas never auto-emits FFMA2) ----
__device__ __forceinline__ unsigned long long bcast2(float a) {
    unsigned long long r;
    asm("mov.b64 %0, {%1, %1};" : "=l"(r) : "f"(a));
    return r;
}
__device__ __forceinline__ void fma2(unsigned long long& acc,
                                     unsigned long long a, unsigned long long b) {
    asm("fma.rn.f32x2 %0, %1, %2, %0;" : "+l"(acc) : "l"(a), "l"(b));
}
__device__ __forceinline__ void add2(unsigned long long& acc, unsigned long long b) {
    asm("add.rn.f32x2 %0, %0, %1;" : "+l"(acc) : "l"(b));
}
__device__ __forceinline__ void unpack2(unsigned long long p, float& lo, float& hi) {
    asm("mov.b64 {%0, %1}, %2;" : "=f"(lo), "=f"(hi) : "l"(p));
}

// ============ convert + count + inline dtype detection ============
// Per-block dtype probe: threads 0..63 each test one of the first 64 int64
// words (512 B — in-bounds under both int32[2E] and int64[2E] layouts since
// the buffer is >= 6.4 MB); __syncthreads_and broadcasts the verdict.
// The degree-count atomicAdd's return value IS the edge's within-node rank.
__global__ void convert_count_kernel(const void* __restrict__ edge, int e, int n) {
    int t = threadIdx.x;
    int i = blockIdx.x * blockDim.x + t;
    const long long* p64 = (const long long*)edge;
    long long probe = 0;
    if (t < 64) probe = p64[t];
    int is64 = __syncthreads_and(t >= 64 || (probe >= 0 && probe < n));

    if (i >= e) return;
    int s, d;
    if (is64) {
        s = (int)p64[i];
        d = (int)p64[e + i];
    } else {
        const int* p = (const int*)edge;
        s = p[i];
        d = p[e + i];
    }
    s = min(max(s, 0), n - 1);
    d = min(max(d, 0), n - 1);
    g_src[i] = s;
    int r = atomicAdd(&g_deg[d], 1);
    g_dst[i] = d | (r << 17);
}

// ============ coalesced scan: bsum -> scan (block offsets inlined) ============
__global__ void bsum_kernel(int n) {
    __shared__ int ws[32];
    int b = blockIdx.x, t = threadIdx.x;
    int lane = t & 31, wid = t >> 5;
    int i = b * SCAN_CHUNK + t;
    int v = (i < n) ? g_deg[i] : 0;
    #pragma unroll
    for (int o = 16; o > 0; o >>= 1) v += __shfl_xor_sync(0xffffffffu, v, o);
    if (lane == 0) ws[wid] = v;
    __syncthreads();
    if (t < 32) {
        int s = ws[t];
        #pragma unroll
        for (int o = 16; o > 0; o >>= 1) s += __shfl_xor_sync(0xffffffffu, s, o);
        if (t == 0) g_bsum[b] = s;
    }
}

// per-chunk exclusive scan; block offset computed in-kernel from g_bsum.
// Also restores g_deg[i] = 0 after consumption (invariant for next replay).
__global__ void scan_kernel(int n, int e) {
    __shared__ int ws[32];
    __shared__ int sOff;
    int b = blockIdx.x, t = threadIdx.x;
    int lane = t & 31, wid = t >> 5;

    if (wid == 0) {
        int off = 0;
        for (int j = lane; j < b; j += 32) off += g_bsum[j];
        #pragma unroll
        for (int o = 16; o > 0; o >>= 1) off += __shfl_xor_sync(0xffffffffu, off, o);
        if (lane == 0) sOff = off;
    }

    int i = b * SCAN_CHUNK + t;
    int v = (i < n) ? g_deg[i] : 0;
    int x = v;
    #pragma unroll
    for (int o = 1; o < 32; o <<= 1) {
        int y = __shfl_up_sync(0xffffffffu, x, o);
        if (lane >= o) x += y;
    }
    if (lane == 31) ws[wid] = x;
    __syncthreads();
    if (wid == 0) {
        int w = ws[lane];
        #pragma unroll
        for (int o = 1; o < 32; o <<= 1) {
            int y = __shfl_up_sync(0xffffffffu, w, o);
            if (lane >= o) w += y;
        }
        ws[lane] = w;
    }
    __syncthreads();
    int incl = x + (wid > 0 ? ws[wid - 1] : 0);
    int excl = incl - v + sOff;
    if (i < n) {
        g_rowptr[i] = excl;
        g_deg[i] = 0;            // restore invariant for next invocation
    }
    if (b == 0 && t == 0) g_rowptr[n] = e;
}

// atomic-free fill: slot = rowptr[dst] + rank (rank packed in g_dst)
__global__ void fill_kernel(int e) {
    int i = blockIdx.x * blockDim.x + threadIdx.x;
    if (i < e) {
        int v = g_dst[i];
        int d = v & DSTMASK;
        int r = v >> 17;
        g_col[g_rowptr[d] + r] = g_src[i];
    }
}

// ================= fused layer (round-10 winner, unchanged) =================
// mode 0: in = x param, out = g_h1, epilogue leaky_relu(0.01)
// mode 1: in = g_h1,    out = out param, epilogue row-L2-normalize
__global__ __launch_bounds__(256) void layer_kernel(
    const float* __restrict__ in_p,
    const float* __restrict__ Wl,      // [64,64] row-major
    const float* __restrict__ bias,    // [64]
    const float* __restrict__ Wr,      // [64,64] row-major
    float* __restrict__ out_p,
    int n, int mode)
{
    __shared__ float sA[NPB * AP];     // [64 nodes][64 k] row-major
    __shared__ float sW[64 * WP];      // [64 k][64 j] transposed weight
    __shared__ float sB[64];

    const float* __restrict__ in = (mode == 0) ? in_p : g_h1;
    float* __restrict__ out      = (mode == 0) ? g_h1 : out_p;

    const unsigned full = 0xffffffffu;
    int t = threadIdx.x;
    int wid = t >> 5, lane = t & 31;
    int half = lane >> 4;        // 0/1: which edge of the pair
    int c4 = (lane & 15) * 4;    // float4 column group
    int node0 = blockIdx.x * NPB;

    // load Wl^T and bias
    for (int idx = t; idx < 64 * 64; idx += 256) {
        int j = idx >> 6, k = idx & 63;
        sW[k * WP + j] = Wl[idx];
    }
    if (t < 64) sB[t] = bias[t];

    // ---- prefetch rowptr for this warp's 8 nodes (lanes 0..15) ----
    int pidx;
    if (lane < 8)       pidx = node0 + wid + lane * 8;
    else if (lane < 16) pidx = node0 + wid + (lane - 8) * 8 + 1;
    else                pidx = n;
    pidx = min(pidx, n);
    int rp = g_rowptr[pidx];

    // ---- prefetch self rows x[node] for all 8 nodes ----
    float2 xs[8];
    #pragma unroll
    for (int it = 0; it < 8; it++) {
        int node = min(node0 + wid + it * 8, n - 1);
        xs[it] = *(const float2*)&in[(size_t)node * 64 + 2 * lane];
    }

    // ---- phase 1: mean aggregation -> sA ----
    #pragma unroll
    for (int it = 0; it < 8; it++) {
        int ni = wid + it * 8;
        int node = node0 + ni;
        float4 a0 = {0.f, 0.f, 0.f, 0.f}, a1 = {0.f, 0.f, 0.f, 0.f};
        int beg = __shfl_sync(full, rp, it);
        int end = __shfl_sync(full, rp, it + 8);
        if (node < n) {
            int e0 = beg;
            for (; e0 + 4 <= end; e0 += 4) {
                int sa = g_col[e0 + half];
                int sb = g_col[e0 + 2 + half];
                float4 v0 = *(const float4*)&in[(size_t)sa * 64 + c4];
                float4 v1 = *(const float4*)&in[(size_t)sb * 64 + c4];
                a0.x += v0.x; a0.y += v0.y; a0.z += v0.z; a0.w += v0.w;
                a1.x += v1.x; a1.y += v1.y; a1.z += v1.z; a1.w += v1.w;
            }
            if (e0 + 2 <= end) {
                int sa = g_col[e0 + half];
                float4 v0 = *(const float4*)&in[(size_t)sa * 64 + c4];
                a0.x += v0.x; a0.y += v0.y; a0.z += v0.z; a0.w += v0.w;
                e0 += 2;
            }
            if (e0 < end && half == 0) {
                int sa = g_col[e0];
                float4 v0 = *(const float4*)&in[(size_t)sa * 64 + c4];
                a1.x += v0.x; a1.y += v0.y; a1.z += v0.z; a1.w += v0.w;
            }
            a0.x += a1.x; a0.y += a1.y; a0.z += a1.z; a0.w += a1.w;
            a0.x += __shfl_xor_sync(full, a0.x, 16);
            a0.y += __shfl_xor_sync(full, a0.y, 16);
            a0.z += __shfl_xor_sync(full, a0.z, 16);
            a0.w += __shfl_xor_sync(full, a0.w, 16);
            int deg = end - beg;
            float inv = 1.0f / (float)(deg > 0 ? deg : 1);
            a0.x *= inv; a0.y *= inv; a0.z *= inv; a0.w *= inv;
        }
        if (half == 0)
            *(float4*)&sA[ni * AP + c4] = a0;
    }
    __syncthreads();

    // ---- GEMM with packed f32x2 accumulators (4x4 tile) ----
    int rg = t >> 4, cg = t & 15;
    int i0 = rg * 4, j0 = cg * 4;
    unsigned long long accp[4][2] = {};

    // pass 1: acc += mean @ Wl^T
    #pragma unroll 4
    for (int k = 0; k < 64; k += 4) {
        float4 a0 = *(const float4*)&sA[(i0 + 0) * AP + k];
        float4 a1 = *(const float4*)&sA[(i0 + 1) * AP + k];
        float4 a2 = *(const float4*)&sA[(i0 + 2) * AP + k];
        float4 a3 = *(const float4*)&sA[(i0 + 3) * AP + k];
        #pragma unroll
        for (int kk = 0; kk < 4; kk++) {
            ulonglong2 wp = *(const ulonglong2*)&sW[(k + kk) * WP + j0];
            float s0 = (kk == 0) ? a0.x : (kk == 1) ? a0.y : (kk == 2) ? a0.z : a0.w;
            float s1 = (kk == 0) ? a1.x : (kk == 1) ? a1.y : (kk == 2) ? a1.z : a1.w;
            float s2 = (kk == 0) ? a2.x : (kk == 1) ? a2.y : (kk == 2) ? a2.z : a2.w;
            float s3 = (kk == 0) ? a3.x : (kk == 1) ? a3.y : (kk == 2) ? a3.z : a3.w;
            unsigned long long p;
            p = bcast2(s0); fma2(accp[0][0], p, wp.x); fma2(accp[0][1], p, wp.y);
            p = bcast2(s1); fma2(accp[1][0], p, wp.x); fma2(accp[1][1], p, wp.y);
            p = bcast2(s2); fma2(accp[2][0], p, wp.x); fma2(accp[2][1], p, wp.y);
            p = bcast2(s3); fma2(accp[3][0], p, wp.x); fma2(accp[3][1], p, wp.y);
        }
    }
    __syncthreads();

    // swap operands: sA <- x, sW <- Wr^T
    #pragma unroll
    for (int it = 0; it < 8; it++) {
        int ni = wid + it * 8;
        *(float2*)&sA[ni * AP + 2 * lane] = xs[it];
    }
    for (int idx = t; idx < 64 * 64; idx += 256) {
        int j = idx >> 6, k = idx & 63;
        sW[k * WP + j] = Wr[idx];
    }
    __syncthreads();

    // pass 2: acc += x @ Wr^T
    #pragma unroll 4
    for (int k = 0; k < 64; k += 4) {
        float4 a0 = *(const float4*)&sA[(i0 + 0) * AP + k];
        float4 a1 = *(const float4*)&sA[(i0 + 1) * AP + k];
        float4 a2 = *(const float4*)&sA[(i0 + 2) * AP + k];
        float4 a3 = *(const float4*)&sA[(i0 + 3) * AP + k];
        #pragma unroll
        for (int kk = 0; kk < 4; kk++) {
            ulonglong2 wp = *(const ulonglong2*)&sW[(k + kk) * WP + j0];
            float s0 = (kk == 0) ? a0.x : (kk == 1) ? a0.y : (kk == 2) ? a0.z : a0.w;
            float s1 = (kk == 0) ? a1.x : (kk == 1) ? a1.y : (kk == 2) ? a1.z : a1.w;
            float s2 = (kk == 0) ? a2.x : (kk == 1) ? a2.y : (kk == 2) ? a2.z : a2.w;
            float s3 = (kk == 0) ? a3.x : (kk == 1) ? a3.y : (kk == 2) ? a3.z : a3.w;
            unsigned long long p;
            p = bcast2(s0); fma2(accp[0][0], p, wp.x); fma2(accp[0][1], p, wp.y);
            p = bcast2(s1); fma2(accp[1][0], p, wp.x); fma2(accp[1][1], p, wp.y);
            p = bcast2(s2); fma2(accp[2][0], p, wp.x); fma2(accp[2][1], p, wp.y);
            p = bcast2(s3); fma2(accp[3][0], p, wp.x); fma2(accp[3][1], p, wp.y);
        }
    }

    // bias (packed) + unpack
    ulonglong2 bp = *(const ulonglong2*)&sB[j0];
    float acc[4][4];
    #pragma unroll
    for (int r = 0; r < 4; r++) {
        add2(accp[r][0], bp.x);
        add2(accp[r][1], bp.y);
        unpack2(accp[r][0], acc[r][0], acc[r][1]);
        unpack2(accp[r][1], acc[r][2], acc[r][3]);
    }

    if (mode == 0) {
        #pragma unroll
        for (int r = 0; r < 4; r++) {
            int node = node0 + i0 + r;
            if (node < n) {
                float4 st; float v;
                v = acc[r][0]; st.x = (v >= 0.f) ? v : 0.01f * v;
                v = acc[r][1]; st.y = (v >= 0.f) ? v : 0.01f * v;
                v = acc[r][2]; st.z = (v >= 0.f) ? v : 0.01f * v;
                v = acc[r][3]; st.w = (v >= 0.f) ? v : 0.01f * v;
                *(float4*)&out[(size_t)node * 64 + j0] = st;
            }
        }
    } else {
        // stage into sA, per-row L2 normalize
        __syncthreads();
        #pragma unroll
        for (int r = 0; r < 4; r++)
            *(float4*)&sA[(i0 + r) * AP + j0] =
                make_float4(acc[r][0], acc[r][1], acc[r][2], acc[r][3]);
        __syncthreads();
        #pragma unroll
        for (int it = 0; it < 8; it++) {
            int ni = wid + it * 8;
            int node = node0 + ni;
            if (node >= n) continue;
            float2 v = *(const float2*)&sA[ni * AP + 2 * lane];
            float ss = v.x * v.x + v.y * v.y;
            #pragma unroll
            for (int o = 16; o > 0; o >>= 1)
                ss += __shfl_xor_sync(full, ss, o);
            float s = 1.0f / fmaxf(sqrtf(ss), 1e-12f);
            *(float2*)&out[(size_t)node * 64 + 2 * lane] =
                make_float2(v.x * s, v.y * s);
        }
    }
}

// ================= launch (kernels ONLY — no host API calls) =================
extern "C" void kernel_launch(void* const* d_in, const int* in_sizes, int n_in,
                              void* d_out, int out_size)
{
    const float* x    = (const float*)d_in[0];
    const void*  edge = (const void*)d_in[1];
    // d_in[2] = edge_weight (ignored by SAGEConv)
    const float* W1l = (const float*)d_in[3];
    const float* b1  = (const float*)d_in[4];
    const float* W1r = (const float*)d_in[5];
    const float* W2l = (const float*)d_in[6];
    const float* b2  = (const float*)d_in[7];
    const float* W2r = (const float*)d_in[8];
    float* out = (float*)d_out;

    int n = in_sizes[0] / DD;
    int e = in_sizes[1] / 2;
    int nb = (n + SCAN_CHUNK - 1) / SCAN_CHUNK;

    convert_count_kernel<<<(e + 255) / 256, 256>>>(edge, e, n);
    bsum_kernel<<<nb, SCAN_CHUNK>>>(n);
    scan_kernel<<<nb, SCAN_CHUNK>>>(n, e);
    fill_kernel<<<(e + 255) / 256, 256>>>(e);

    int nblocks = (n + NPB - 1) / NPB;
    layer_kernel<<<nblocks, 256>>>(x, W1l, b1, W1r, nullptr, n, 0); // -> g_h1
    layer_kernel<<<nblocks, 256>>>(x, W2l, b2, W2r, out,     n, 1); // g_h1 -> out
}